// round 17
// baseline (speedup 1.0000x reference)
#include <cuda_runtime.h>
#include <cuda_fp16.h>
#include <cstdint>
#include <math.h>

#define NB 4
#define NC 256
#define NN 4096

// fp16 smem strides (elements)
#define SQK 264    // Q/K rows: 528B -> ldmatrix conflict-free
#define SVP 72     // V / P rows: 144B -> conflict-free
#define SSTR2 132  // fp32 Ot stride (128 queries + pad)

// flash smem byte offsets (BM=128; K 2-stage, V 2-stage)
#define OFF_Q    0
#define OFF_K    67584
#define KSTAGE   33792
#define OFF_V    135168
#define VSTAGE   36864
#define OFF_P    208896
#define OFF_PMAX 227328
#define OFF_LPART 228352
#define OFF_SCAL 229376
#define SMEM_BYTES 229888

// gemm smem: A tile + B tile, 64 x 264 fp16 each
#define GEMM_SMEM (2*64*SQK*2)

// scratch: q,k as (B,N,C) fp16; v as (B,C,N) fp16; xh as (B,N,C) fp16
__device__ __half g_q[NB*NN*NC];
__device__ __half g_k[NB*NN*NC];
__device__ __half g_v[NB*NN*NC];
__device__ __half g_xh[NB*NN*NC];
__device__ __half g_wh[3*NC*NC];

__device__ __forceinline__ uint32_t pack2(float a, float b) {
    __half2 h = __floats2half2_rn(a, b);
    return *(uint32_t*)&h;
}
__device__ __forceinline__ uint32_t smem_u32(const void* p) {
    uint32_t a;
    asm("{ .reg .u64 t; cvta.to.shared.u64 t, %1; cvt.u32.u64 %0, t; }" : "=r"(a) : "l"(p));
    return a;
}
__device__ __forceinline__ void ldsm4(uint32_t& r0, uint32_t& r1, uint32_t& r2,
                                      uint32_t& r3, uint32_t addr) {
    asm volatile("ldmatrix.sync.aligned.m8n8.x4.shared.b16 {%0,%1,%2,%3}, [%4];"
                 : "=r"(r0), "=r"(r1), "=r"(r2), "=r"(r3) : "r"(addr));
}
__device__ __forceinline__ void mma_f16(float* c, const uint32_t* a,
                                        uint32_t b0, uint32_t b1) {
    asm volatile(
        "mma.sync.aligned.m16n8k16.row.col.f32.f16.f16.f32 "
        "{%0,%1,%2,%3}, {%4,%5,%6,%7}, {%8,%9}, {%0,%1,%2,%3};"
        : "+f"(c[0]), "+f"(c[1]), "+f"(c[2]), "+f"(c[3])
        : "r"(a[0]), "r"(a[1]), "r"(a[2]), "r"(a[3]), "r"(b0), "r"(b1));
}
__device__ __forceinline__ void cp16(uint32_t saddr, const void* gaddr) {
    asm volatile("cp.async.cg.shared.global [%0], [%1], 16;"
                 :: "r"(saddr), "l"(gaddr));
}
#define CP_COMMIT()   asm volatile("cp.async.commit_group;" ::: "memory")
#define CP_WAIT(n)    asm volatile("cp.async.wait_group %0;" :: "n"(n) : "memory")
#define BAR_PAIR(id)  asm volatile("bar.sync %0, 64;" :: "r"(id) : "memory")
#define BAR_SYNC384(id)   asm volatile("bar.sync %0, 384;" :: "r"(id) : "memory")
#define BAR_ARRIVE384(id) asm volatile("bar.arrive %0, 384;" :: "r"(id) : "memory")

// ---------------------------------------------------------------------------
// Prep: W -> fp16 (Wq pre-scaled by log2(e)) and x (B,C,N) -> xh (B,N,C) fp16.
// Blocks [0,768): wconv. Blocks [768, 768+1024): x transpose tiles.
// ---------------------------------------------------------------------------
__global__ __launch_bounds__(256)
void prep_kernel(const float* __restrict__ x,
                 const float* __restrict__ Wq,
                 const float* __restrict__ Wk,
                 const float* __restrict__ Wv)
{
    if (blockIdx.x < 768) {
        int i = blockIdx.x * 256 + threadIdx.x;   // < 3*65536
        const float* src = (i < 65536) ? Wq : (i < 131072) ? Wk : Wv;
        int o = i & 65535;
        float v = src[o];
        if (i < 65536) v *= 1.44269504f;
        g_wh[i] = __float2half(v);
        return;
    }

    __shared__ float ts[64][65];
    const int bid = blockIdx.x - 768;
    const int n0 = (bid & 63) * 64;
    const int c0 = ((bid >> 6) & 3) * 64;
    const int b  = bid >> 8;
    const int t  = threadIdx.x;

    #pragma unroll
    for (int it = 0; it < 4; it++) {
        int i = t + it*256;
        int c = i >> 4, nq = i & 15;
        float4 v = *(const float4*)&x[(size_t)(b*NC + c0 + c)*NN + n0 + nq*4];
        ts[nq*4 + 0][c] = v.x;
        ts[nq*4 + 1][c] = v.y;
        ts[nq*4 + 2][c] = v.z;
        ts[nq*4 + 3][c] = v.w;
    }
    __syncthreads();

    #pragma unroll
    for (int it = 0; it < 2; it++) {
        int i = t + it*256;
        int n = i >> 3, cq = i & 7;
        uint4 o;
        o.x = pack2(ts[n][cq*8 + 0], ts[n][cq*8 + 1]);
        o.y = pack2(ts[n][cq*8 + 2], ts[n][cq*8 + 3]);
        o.z = pack2(ts[n][cq*8 + 4], ts[n][cq*8 + 5]);
        o.w = pack2(ts[n][cq*8 + 6], ts[n][cq*8 + 7]);
        *(uint4*)&g_xh[(size_t)(b*NN + n0 + n)*NC + c0 + cq*8] = o;
    }
}

// ---------------------------------------------------------------------------
// QKV projection GEMM (fp16 mma). grid (256, 4, 3), 256 threads.
// ---------------------------------------------------------------------------
__global__ __launch_bounds__(256, 3)
void qkv_mma_kernel()
{
    extern __shared__ char smem[];
    const uint32_t sb = smem_u32(smem);
    const uint32_t SB_OFF = 64*SQK*2;

    const int bx = blockIdx.x;
    const int by = blockIdx.y;
    const int z  = blockIdx.z;

    const __half* Aptr;
    const __half* Bptr;
    if (z < 2) {
        Aptr = g_xh + (size_t)bx*64*NC;
        Bptr = g_wh + (size_t)z*65536 + (size_t)by*64*NC;
    } else {
        Aptr = g_wh + 2*65536 + (size_t)by*64*NC;
        Bptr = g_xh + (size_t)bx*64*NC;
    }

    const int t    = threadIdx.x;
    const int w    = t >> 5;
    const int lane = t & 31;
    const int gid  = lane >> 2;
    const int tig  = lane & 3;
    const int wr   = w >> 1;
    const int wcl  = w & 1;
    const int lrow = lane & 15;
    const int lk   = (lane >> 4) * 8;

    #pragma unroll
    for (int it = 0; it < 8; it++) {
        int i = t + it*256;
        int r = i >> 5, gq = i & 31;
        *(uint4*)(smem + r*(SQK*2) + gq*16) =
            ((const uint4*)(Aptr + (size_t)r*NC))[gq];
        *(uint4*)(smem + SB_OFF + r*(SQK*2) + gq*16) =
            ((const uint4*)(Bptr + (size_t)r*NC))[gq];
    }
    __syncthreads();

    float sacc[4][4];
    #pragma unroll
    for (int j = 0; j < 4; j++)
        #pragma unroll
        for (int r = 0; r < 4; r++) sacc[j][r] = 0.f;

    const uint32_t aa = sb + ((16*wr + lrow)*SQK + lk)*2;
    const uint32_t ba = sb + SB_OFF + ((32*wcl + lrow)*SQK + lk)*2;

    #pragma unroll
    for (int s = 0; s < 16; s++) {
        uint32_t a[4], b0, b1, b2, b3, c0, c1, c2, c3;
        ldsm4(a[0], a[1], a[2], a[3], aa + 32*s);
        ldsm4(b0, b1, b2, b3, ba + 32*s);
        ldsm4(c0, c1, c2, c3, ba + 16*(SQK*2) + 32*s);
        mma_f16(sacc[0], a, b0, b2);
        mma_f16(sacc[1], a, b1, b3);
        mma_f16(sacc[2], a, c0, c2);
        mma_f16(sacc[3], a, c1, c3);
    }

    #pragma unroll
    for (int mh = 0; mh < 2; mh++) {
        const int mrow = 16*wr + gid + 8*mh;
        if (z < 2) {
            __half* D = (z == 0) ? g_q : g_k;
            const size_t rb = ((size_t)bx*64 + mrow)*NC + by*64;
            #pragma unroll
            for (int j = 0; j < 4; j++)
                *(uint32_t*)&D[rb + 32*wcl + 8*j + 2*tig] =
                    pack2(sacc[j][2*mh], sacc[j][2*mh + 1]);
        } else {
            const int bb = bx >> 6;
            const int nl = (bx & 63)*64;
            const size_t rb = (size_t)bb*NC*NN + ((size_t)by*64 + mrow)*NN + nl;
            #pragma unroll
            for (int j = 0; j < 4; j++)
                *(uint32_t*)&g_v[rb + 32*wcl + 8*j + 2*tig] =
                    pack2(sacc[j][2*mh], sacc[j][2*mh + 1]);
        }
    }
}

// ---------------------------------------------------------------------------
// Fused flash attention, BM=128, BN=64, 512 threads, 1 wave.
// K + V both 2-stage cp.async; bar1 fences K+V; P publication via two
// 384-thread partial barriers (producers arrive, consumers sync).
// ---------------------------------------------------------------------------
__global__ __launch_bounds__(512, 1)
void flash_kernel(const float* __restrict__ x,
                  const float* __restrict__ gamma,
                  float* __restrict__ out)
{
    extern __shared__ char smem[];
    const uint32_t sb = smem_u32(smem);
    float* pmax   = (float*)(smem + OFF_PMAX);    // [2][128]
    float* lpart  = (float*)(smem + OFF_LPART);   // [2][128]
    float* s_scal = (float*)(smem + OFF_SCAL);    // [128]

    const int b    = blockIdx.y;
    const int n0   = blockIdx.x * 128;
    const int t    = threadIdx.x;
    const int w    = t >> 5;      // 0..15
    const int lane = t & 31;
    const int gid  = lane >> 2;
    const int tig  = lane & 3;
    const int wr   = w >> 1;      // 0..7
    const int wcl  = w & 1;       // 0..1
    const int lrow = lane & 15;
    const int lk   = (lane >> 4) * 8;

    const int kr = t >> 5, kq = t & 31;
    const int vc = t >> 3, vu = t & 7;

    const __half* kg_b = g_k + (size_t)b*NN*NC;
    const __half* vg_b = g_v + (size_t)b*NC*NN;

    // load Q tile (128 x 256 fp16)
    {
        const uint4* qg = (const uint4*)(g_q + (size_t)(b*NN + n0)*NC);
        #pragma unroll
        for (int it = 0; it < 8; it++) {
            int i = t + it*512;
            int r = i >> 5, gq = i & 31;
            *(uint4*)(smem + OFF_Q + r*(SQK*2) + gq*16) = qg[i];
        }
    }

    // prologue: K0 (group), V0 (group) into stage 0
    {
        #pragma unroll
        for (int it = 0; it < 4; it++) {
            int r = kr + it*16;
            cp16(sb + OFF_K + r*(SQK*2) + kq*16, kg_b + (size_t)r*NC + kq*8);
        }
        CP_COMMIT();
        #pragma unroll
        for (int it = 0; it < 4; it++) {
            int c = vc + it*64;
            cp16(sb + OFF_V + c*(SVP*2) + vu*16, vg_b + (size_t)c*NN + vu*8);
        }
        CP_COMMIT();
    }

    const int r0 = 16*wr + gid;
    float m_prev[2] = {-INFINITY, -INFINITY};
    float l_acc[2]  = {0.f, 0.f};

    float o[2][8][4];
    #pragma unroll
    for (int mt = 0; mt < 2; mt++)
        #pragma unroll
        for (int nt = 0; nt < 8; nt++)
            #pragma unroll
            for (int r = 0; r < 4; r++) o[mt][nt][r] = 0.f;

    const uint32_t qa_base = sb + OFF_Q + ((16*wr + lrow)*SQK + lk)*2;
    const uint32_t ka_off  = ((32*wcl + lrow)*SQK + lk)*2;
    const uint32_t va_off  = ((32*wr + lrow)*SVP + lk)*2;
    uint32_t pa_base[4];
    #pragma unroll
    for (int jq = 0; jq < 4; jq++)
        pa_base[jq] = sb + OFF_P + ((64*wcl + 16*jq + lrow)*SVP + lk)*2;

    for (int kt = 0; kt < 64; kt++) {
        // commit K(t+1), then wait for K(t) AND V(t) [pending allowed: K(t+1)]
        if (kt < 63) {
            const __half* kgp = kg_b + (size_t)(kt + 1)*64*NC;
            const uint32_t kbase = sb + OFF_K + ((kt + 1) & 1)*KSTAGE;
            #pragma unroll
            for (int it = 0; it < 4; it++) {
                int r = kr + it*16;
                cp16(kbase + r*(SQK*2) + kq*16, kgp + (size_t)r*NC + kq*8);
            }
            CP_COMMIT();
            CP_WAIT(1);
        } else {
            CP_WAIT(0);
        }
        __syncthreads();   // bar1: K(t) + V(t) visible; PV(t-1) globally complete

        // issue V(t+1) into other stage (overlaps S+softmax+PV)
        if (kt < 63) {
            const __half* vgp = vg_b + (size_t)(kt + 1)*64;
            const uint32_t vbase = sb + OFF_V + ((kt + 1) & 1)*VSTAGE;
            #pragma unroll
            for (int it = 0; it < 4; it++) {
                int c = vc + it*64;
                cp16(vbase + c*(SVP*2) + vu*16, vgp + (size_t)c*NN + vu*8);
            }
            CP_COMMIT();
        }

        const uint32_t ka_base = sb + OFF_K + (kt & 1)*KSTAGE + ka_off;
        const uint32_t va_base = sb + OFF_V + (kt & 1)*VSTAGE + va_off;

        // --- S = Q K^T (base-2 logits) ---
        float sacc[4][4];
        #pragma unroll
        for (int j = 0; j < 4; j++)
            #pragma unroll
            for (int r = 0; r < 4; r++) sacc[j][r] = 0.f;

        #pragma unroll
        for (int s = 0; s < 16; s++) {
            uint32_t a[4], b0, b1, b2, b3, c0, c1, c2, c3;
            ldsm4(a[0], a[1], a[2], a[3], qa_base + 32*s);
            ldsm4(b0, b1, b2, b3, ka_base + 32*s);
            ldsm4(c0, c1, c2, c3, ka_base + 16*(SQK*2) + 32*s);
            mma_f16(sacc[0], a, b0, b2);
            mma_f16(sacc[1], a, b1, b3);
            mma_f16(sacc[2], a, c0, c2);
            mma_f16(sacc[3], a, c1, c3);
        }

        // warp-partial row max -> pair exchange via named barrier
        {
            float mx0 = fmaxf(fmaxf(sacc[0][0], sacc[0][1]), fmaxf(sacc[1][0], sacc[1][1]));
            mx0 = fmaxf(mx0, fmaxf(fmaxf(sacc[2][0], sacc[2][1]), fmaxf(sacc[3][0], sacc[3][1])));
            float mx1 = fmaxf(fmaxf(sacc[0][2], sacc[0][3]), fmaxf(sacc[1][2], sacc[1][3]));
            mx1 = fmaxf(mx1, fmaxf(fmaxf(sacc[2][2], sacc[2][3]), fmaxf(sacc[3][2], sacc[3][3])));
            mx0 = fmaxf(mx0, __shfl_xor_sync(0xffffffffu, mx0, 1));
            mx0 = fmaxf(mx0, __shfl_xor_sync(0xffffffffu, mx0, 2));
            mx1 = fmaxf(mx1, __shfl_xor_sync(0xffffffffu, mx1, 1));
            mx1 = fmaxf(mx1, __shfl_xor_sync(0xffffffffu, mx1, 2));
            if (tig == 0) {
                pmax[wcl*128 + r0]     = mx0;
                pmax[wcl*128 + r0 + 8] = mx1;
            }
        }
        BAR_PAIR(wr + 1);   // 2-warp exchange (rows 16wr..+16)

        // --- softmax (base-2, lazy l) ---
        {
            float m_new0 = fmaxf(m_prev[0], fmaxf(pmax[r0],     pmax[128 + r0]));
            float m_new1 = fmaxf(m_prev[1], fmaxf(pmax[r0 + 8], pmax[128 + r0 + 8]));
            float corr0 = exp2f(m_prev[0] - m_new0);
            float corr1 = exp2f(m_prev[1] - m_new1);
            m_prev[0] = m_new0; m_prev[1] = m_new1;

            float ps0 = 0.f, ps1 = 0.f;
            #pragma unroll
            for (int j = 0; j < 4; j++) {
                float p0 = exp2f(sacc[j][0] - m_new0);
                float p1 = exp2f(sacc[j][1] - m_new0);
                float p2 = exp2f(sacc[j][2] - m_new1);
                float p3 = exp2f(sacc[j][3] - m_new1);
                ps0 += p0 + p1; ps1 += p2 + p3;
                int cj = 32*wcl + 8*j + 2*tig;
                *(uint32_t*)(smem + OFF_P + (r0*SVP + cj)*2)       = pack2(p0, p1);
                *(uint32_t*)(smem + OFF_P + ((r0 + 8)*SVP + cj)*2) = pack2(p2, p3);
            }
            l_acc[0] = l_acc[0]*corr0 + ps0;
            l_acc[1] = l_acc[1]*corr1 + ps1;
            if (wcl == 0 && tig == 0) {
                s_scal[r0]     = corr0;
                s_scal[r0 + 8] = corr1;
            }
        }

        // partial barriers: P rows 0-63 (group A, id 9) / rows 64-127 (B, id 10)
        // producers: wr<4 -> A, wr>=4 -> B. consumers: wcl==0 -> A, wcl==1 -> B.
        if (wr < 4) {
            if (wcl == 0) { BAR_SYNC384(9); }            // prod A + cons A
            else          { BAR_ARRIVE384(9); BAR_SYNC384(10); }  // prod A, cons B
        } else {
            if (wcl == 0) { BAR_ARRIVE384(10); BAR_SYNC384(9); }  // prod B, cons A
            else          { BAR_SYNC384(10); }           // prod B + cons B
        }

        // --- O^T = O^T*corr + V^T P^T (skip rescale when corr==1) ---
        {
            float sc0[8], sc1[8];
            float need = 0.f;
            #pragma unroll
            for (int nt = 0; nt < 8; nt++) {
                sc0[nt] = s_scal[64*wcl + 8*nt + 2*tig];
                sc1[nt] = s_scal[64*wcl + 8*nt + 2*tig + 1];
                need += fabsf(sc0[nt] - 1.f) + fabsf(sc1[nt] - 1.f);
            }
            if (need != 0.f) {
                #pragma unroll
                for (int nt = 0; nt < 8; nt++)
                    #pragma unroll
                    for (int mt = 0; mt < 2; mt++) {
                        o[mt][nt][0] *= sc0[nt]; o[mt][nt][1] *= sc1[nt];
                        o[mt][nt][2] *= sc0[nt]; o[mt][nt][3] *= sc1[nt];
                    }
            }
        }
        #pragma unroll
        for (int s = 0; s < 4; s++) {
            uint32_t av0[4], av1[4];
            ldsm4(av0[0], av0[1], av0[2], av0[3], va_base + 32*s);
            ldsm4(av1[0], av1[1], av1[2], av1[3], va_base + 16*(SVP*2) + 32*s);
            #pragma unroll
            for (int jq = 0; jq < 4; jq++) {
                uint32_t p0, p1, p2, p3;
                ldsm4(p0, p1, p2, p3, pa_base[jq] + 32*s);
                mma_f16(o[0][2*jq],     av0, p0, p2);
                mma_f16(o[0][2*jq + 1], av0, p1, p3);
                mma_f16(o[1][2*jq],     av1, p0, p2);
                mma_f16(o[1][2*jq + 1], av1, p1, p3);
            }
        }
        // P / s_scal / V reuse hazards fenced by bar1 of next iteration
    }

    // final l: reduce over tig lanes, then across wcl via smem
    {
        float l0 = l_acc[0], l1 = l_acc[1];
        l0 += __shfl_xor_sync(0xffffffffu, l0, 1);
        l0 += __shfl_xor_sync(0xffffffffu, l0, 2);
        l1 += __shfl_xor_sync(0xffffffffu, l1, 1);
        l1 += __shfl_xor_sync(0xffffffffu, l1, 2);
        if (tig == 0) {
            lpart[wcl*128 + r0]     = l0;
            lpart[wcl*128 + r0 + 8] = l1;
        }
    }
    __syncthreads();

    // --- O^T/l to Ot smem (channel-major) ---
    float* Ot = (float*)(smem + OFF_Q);
    #pragma unroll
    for (int nt = 0; nt < 8; nt++) {
        int q = 64*wcl + 8*nt + 2*tig;
        float li0 = __fdividef(1.f, lpart[q]     + lpart[128 + q]);
        float li1 = __fdividef(1.f, lpart[q + 1] + lpart[128 + q + 1]);
        #pragma unroll
        for (int mt = 0; mt < 2; mt++) {
            int c = 32*wr + 16*mt + gid;
            Ot[c*SSTR2 + q]         = o[mt][nt][0] * li0;
            Ot[c*SSTR2 + q + 1]     = o[mt][nt][1] * li1;
            Ot[(c+8)*SSTR2 + q]     = o[mt][nt][2] * li0;
            Ot[(c+8)*SSTR2 + q + 1] = o[mt][nt][3] * li1;
        }
    }
    __syncthreads();

    const float g = gamma[0];
    #pragma unroll
    for (int pass = 0; pass < 2; pass++) {
        int c = pass*128 + (t >> 2);
        #pragma unroll
        for (int j = 0; j < 8; j++) {
            int f4 = (t & 3) + j*4;
            float4 ov = *(float4*)(Ot + c*SSTR2 + f4*4);
            float4 xv = *(const float4*)(x + (size_t)(b*NC + c)*NN + n0 + f4*4);
            float4 r;
            r.x = g*ov.x + xv.x; r.y = g*ov.y + xv.y;
            r.z = g*ov.z + xv.z; r.w = g*ov.w + xv.w;
            *(float4*)(out + (size_t)(b*NC + c)*NN + n0 + f4*4) = r;
        }
    }
}

// ---------------------------------------------------------------------------

extern "C" void kernel_launch(void* const* d_in, const int* in_sizes, int n_in,
                              void* d_out, int out_size)
{
    const float* x     = (const float*)d_in[0];
    const float* Wq    = (const float*)d_in[1];
    const float* Wk    = (const float*)d_in[2];
    const float* Wv    = (const float*)d_in[3];
    const float* gamma = (const float*)d_in[4];
    float* out = (float*)d_out;

    cudaFuncSetAttribute(flash_kernel,
                         cudaFuncAttributeMaxDynamicSharedMemorySize, SMEM_BYTES);
    cudaFuncSetAttribute(qkv_mma_kernel,
                         cudaFuncAttributeMaxDynamicSharedMemorySize, GEMM_SMEM);

    prep_kernel<<<768 + 1024, 256>>>(x, Wq, Wk, Wv);

    dim3 gg(256, 4, 3);
    qkv_mma_kernel<<<gg, 256, GEMM_SMEM>>>();

    dim3 gf(NN/128, NB);
    flash_kernel<<<gf, 512, SMEM_BYTES>>>(x, gamma, out);
}